// round 6
// baseline (speedup 1.0000x reference)
#include <cuda_runtime.h>
#include <cuda_bf16.h>

// Problem constants
#define BATCH 4
#define CIN   64
#define HH    128
#define WW    128
#define OUTC  64
#define K2N   9
#define NPOS  (BATCH*HH*WW)

// Scratch (device globals; no allocation allowed)
__device__ __align__(16) float g_xT[BATCH*HH*WW*CIN];   // [b][y][x][c]
__device__ __align__(16) float g_post[NPOS*28];         // partial half0, then final after combine
__device__ __align__(16) float g_post2[NPOS*28];        // partial half1
__device__ __align__(16) float g_cwT[9*64*28];          // [tap][c][j]
__device__ __align__(16) float g_dwD[9*64*128];         // [k][c][2*o+d] : dup'd deform weights

// ------------------------- f32x2 helpers (sm_100+) -------------------------
__device__ __forceinline__ void ffma2(unsigned long long& d,
                                      unsigned long long a,
                                      unsigned long long b) {
    asm("fma.rn.f32x2 %0, %1, %2, %0;" : "+l"(d) : "l"(a), "l"(b));
}
__device__ __forceinline__ unsigned long long dup2(float a) {
    unsigned long long r;
    asm("mov.b64 %0, {%1, %1};" : "=l"(r) : "f"(a));
    return r;
}

// ---------------------------------------------------------------------------
// Kernel W: weight transposes (tiny)
// ---------------------------------------------------------------------------
__global__ void kW(const float* __restrict__ ow, const float* __restrict__ mw,
                   const float* __restrict__ dw) {
    int i = blockIdx.x * blockDim.x + threadIdx.x;
    int stride = gridDim.x * blockDim.x;
    for (int idx = i; idx < 9*64*28; idx += stride) {
        int j   = idx % 28;
        int c   = (idx / 28) % 64;
        int tap = idx / (28*64);
        float v = 0.f;
        if (j < 18)      v = ow[j*576 + c*9 + tap];
        else if (j < 27) v = mw[(j-18)*576 + c*9 + tap];
        g_cwT[idx] = v;
    }
    // g_dwD[k][c][2*o+d] = dw[o][c][k]
    for (int idx = i; idx < 9*64*128; idx += stride) {
        int o = (idx >> 1) & 63;
        int c = (idx >> 7) & 63;
        int k = idx >> 13;
        g_dwD[idx] = dw[o*576 + c*9 + k];
    }
}

// ---------------------------------------------------------------------------
// Kernel A: NCHW -> NHWC transpose of x  (grid = BATCH*HH, block = 128)
// ---------------------------------------------------------------------------
__global__ __launch_bounds__(128) void kA(const float* __restrict__ x) {
    int by = blockIdx.x;
    int b = by >> 7, y = by & 127;
    int xq = threadIdx.x;
    const float* src = x + ((size_t)(b*CIN)*HH + y) * WW + xq;
    float* dst = g_xT + (((size_t)b*HH + y) * WW + xq) * CIN;
#pragma unroll
    for (int c4 = 0; c4 < 16; ++c4) {
        float4 v;
        v.x = src[(size_t)(c4*4+0)*HH*WW];
        v.y = src[(size_t)(c4*4+1)*HH*WW];
        v.z = src[(size_t)(c4*4+2)*HH*WW];
        v.w = src[(size_t)(c4*4+3)*HH*WW];
        *reinterpret_cast<float4*>(dst + c4*4) = v;
    }
}

// ---------------------------------------------------------------------------
// Kernel B: offset + mask conv partials over a 32-channel half.
// grid = dim3(512, 2): blockIdx.x = (b,y) row, blockIdx.y = channel half.
// Writes RAW accumulators (no bias/sigmoid) to g_post (half0) / g_post2 (half1).
// ---------------------------------------------------------------------------
__global__ __launch_bounds__(128) void kB() {
    __shared__ __align__(16) float sw[32*28];   // weights for one tap, 32 channels
    int by = blockIdx.x;
    int b = by >> 7, y = by & 127;
    int xq = threadIdx.x;
    int c0 = blockIdx.y * 32;
    float* gdst = blockIdx.y ? g_post2 : g_post;

    unsigned long long acc[14];
#pragma unroll
    for (int j = 0; j < 14; ++j) acc[j] = 0ULL;

    for (int tap = 0; tap < 9; ++tap) {
        __syncthreads();
        for (int t = threadIdx.x; t < 32*28/4; t += 128)
            reinterpret_cast<float4*>(sw)[t] =
                reinterpret_cast<const float4*>(g_cwT + tap*64*28 + c0*28)[t];
        __syncthreads();

        int ky = tap / 3, kx = tap % 3;
        int ys = y + ky - 1, xs = xq + kx - 1;
        if (ys < 0 || ys > 127 || xs < 0 || xs > 127) continue;  // zero pad

        const float4* xp = reinterpret_cast<const float4*>(
            g_xT + (((size_t)b*HH + ys) * WW + xs) * CIN + c0);
#pragma unroll 4
        for (int c4 = 0; c4 < 8; ++c4) {
            float4 xv = xp[c4];
#pragma unroll
            for (int cc = 0; cc < 4; ++cc) {
                unsigned long long ad = dup2((&xv.x)[cc]);
                const float4* wp = reinterpret_cast<const float4*>(sw + (c4*4+cc)*28);
#pragma unroll
                for (int j4 = 0; j4 < 7; ++j4) {
                    float4 w = wp[j4];
                    const unsigned long long* wu =
                        reinterpret_cast<const unsigned long long*>(&w);
                    ffma2(acc[j4*2+0], ad, wu[0]);
                    ffma2(acc[j4*2+1], ad, wu[1]);
                }
            }
        }
    }

    float* dst = gdst + (((size_t)(b*HH) + y) * WW + xq) * 28;
#pragma unroll
    for (int j2 = 0; j2 < 14; ++j2)
        *reinterpret_cast<unsigned long long*>(dst + 2*j2) = acc[j2];
}

// ---------------------------------------------------------------------------
// Kernel Bc: combine the two channel-half partials, add bias, sigmoid masks.
// In-place into g_post. grid = 512, block = 128 (thread per position).
// ---------------------------------------------------------------------------
__global__ __launch_bounds__(128) void kBc(const float* __restrict__ ob,
                                           const float* __restrict__ mb) {
    size_t pos = (size_t)blockIdx.x * 128 + threadIdx.x;
    float* a = g_post + pos * 28;
    const float* bpart = g_post2 + pos * 28;
    float r[28];
#pragma unroll
    for (int q = 0; q < 7; ++q) {
        float4 va = reinterpret_cast<const float4*>(a)[q];
        float4 vb = reinterpret_cast<const float4*>(bpart)[q];
        r[4*q+0] = va.x + vb.x; r[4*q+1] = va.y + vb.y;
        r[4*q+2] = va.z + vb.z; r[4*q+3] = va.w + vb.w;
    }
#pragma unroll
    for (int j = 0; j < 18; ++j) r[j] += ob[j];
#pragma unroll
    for (int j = 0; j < 9; ++j) {
        float t = r[18+j] + mb[j];
        r[18+j] = 1.f / (1.f + __expf(-t));
    }
    r[27] = 0.f;
#pragma unroll
    for (int q = 0; q < 7; ++q) {
        float4 v = make_float4(r[4*q+0], r[4*q+1], r[4*q+2], r[4*q+3]);
        reinterpret_cast<float4*>(a)[q] = v;
    }
}

// ---------------------------------------------------------------------------
// Kernel C: bilinear sampling + deform GEMM, FFMA2, single unified pass per k.
// grid = BATCH*HH (one (b,y) row per block), block = 128.
// Smem: A tile [64c][128pos] (32KB) + dup'd W slab [64c][128] (32KB) = 64KB.
// Thread tile: 8 positions (4 strided pairs) x 8 outputs.
// ---------------------------------------------------------------------------
__global__ __launch_bounds__(128) void kC(const float* __restrict__ db,
                                          float* __restrict__ out) {
    __shared__ __align__(16) float A_sh[64][128];
    __shared__ __align__(16) float Wd_sh[64][128];   // [c][2*o+d]

    int by = blockIdx.x;
    int b = by >> 7, y = by & 127;
    int tid  = threadIdx.x;
    int pcol = tid & 15;     // position-pair column: x pairs at pcol*2 + i2*32
    int og   = tid >> 4;     // output group 0..7: o = og*8 + j

    // acc[i2*8 + j] : f32x2 pair over two adjacent x, output o = og*8+j
    unsigned long long acc[32];
#pragma unroll
    for (int j = 0; j < 8; ++j) {
        unsigned long long bd = dup2(db[og*8 + j]);
#pragma unroll
        for (int i2 = 0; i2 < 4; ++i2) acc[i2*8+j] = bd;
    }

    const float* pi = g_post + (((size_t)(b*HH) + y) * WW + tid) * 28;

    for (int k = 0; k < 9; ++k) {
        __syncthreads();  // previous GEMM done reading A_sh / Wd_sh

        // ---- fill W slab for this k (2048 float4 / 128 threads = 16 each) ----
        {
            const float4* src = reinterpret_cast<const float4*>(g_dwD + (size_t)k*8192);
            float4* dst = reinterpret_cast<float4*>(&Wd_sh[0][0]);
#pragma unroll
            for (int t = 0; t < 16; ++t) dst[tid + t*128] = src[tid + t*128];
        }

        // ---- sampling: thread = position tid, write A_sh[c][tid] ----
        {
            float dy = pi[2*k], dx = pi[2*k+1], m = pi[18+k];
            int ky = k / 3, kx = k % 3;
            float py = dy + (float)(ky + y   - 1);
            float px = dx + (float)(kx + tid - 1);
            float fy = floorf(py), fx = floorf(px);
            float wy1 = py - fy, wx1 = px - fx;
            float wy0 = 1.f - wy1, wx0 = 1.f - wx1;
            int y0 = (int)fy, x0 = (int)fx;
            int y1 = y0 + 1, x1 = x0 + 1;
            bool vy0 = (y0 >= 0) & (y0 < HH), vy1 = (y1 >= 0) & (y1 < HH);
            bool vx0 = (x0 >= 0) & (x0 < WW), vx1 = (x1 >= 0) & (x1 < WW);
            float w00 = (vy0 && vx0) ? wy0*wx0*m : 0.f;
            float w01 = (vy0 && vx1) ? wy0*wx1*m : 0.f;
            float w10 = (vy1 && vx0) ? wy1*wx0*m : 0.f;
            float w11 = (vy1 && vx1) ? wy1*wx1*m : 0.f;
            int yc0 = min(max(y0, 0), HH-1), yc1 = min(max(y1, 0), HH-1);
            int xc0 = min(max(x0, 0), WW-1), xc1 = min(max(x1, 0), WW-1);

            const float4* p00 = reinterpret_cast<const float4*>(g_xT + (((size_t)b*HH + yc0)*WW + xc0)*CIN);
            const float4* p01 = reinterpret_cast<const float4*>(g_xT + (((size_t)b*HH + yc0)*WW + xc1)*CIN);
            const float4* p10 = reinterpret_cast<const float4*>(g_xT + (((size_t)b*HH + yc1)*WW + xc0)*CIN);
            const float4* p11 = reinterpret_cast<const float4*>(g_xT + (((size_t)b*HH + yc1)*WW + xc1)*CIN);

#pragma unroll 4
            for (int c4 = 0; c4 < 16; ++c4) {
                float4 a = p00[c4], bb = p01[c4], cv = p10[c4], d = p11[c4];
                A_sh[c4*4+0][tid] = w00*a.x + w01*bb.x + w10*cv.x + w11*d.x;
                A_sh[c4*4+1][tid] = w00*a.y + w01*bb.y + w10*cv.y + w11*d.y;
                A_sh[c4*4+2][tid] = w00*a.z + w01*bb.z + w10*cv.z + w11*d.z;
                A_sh[c4*4+3][tid] = w00*a.w + w01*bb.w + w10*cv.w + w11*d.w;
            }
        }

        __syncthreads();  // A + W ready

        // ---- GEMM: 64 c, 32 ffma2 each ----
#pragma unroll 4
        for (int c = 0; c < 64; ++c) {
            const ulonglong2* wp =
                reinterpret_cast<const ulonglong2*>(&Wd_sh[c][og*16]);
            ulonglong2 wq0 = wp[0], wq1 = wp[1], wq2 = wp[2], wq3 = wp[3];
            const float* ac = &A_sh[c][pcol*2];
            unsigned long long a0 = *reinterpret_cast<const unsigned long long*>(ac);
            unsigned long long a1 = *reinterpret_cast<const unsigned long long*>(ac + 32);
            unsigned long long a2 = *reinterpret_cast<const unsigned long long*>(ac + 64);
            unsigned long long a3 = *reinterpret_cast<const unsigned long long*>(ac + 96);

            ffma2(acc[ 0], a0, wq0.x); ffma2(acc[ 1], a0, wq0.y);
            ffma2(acc[ 2], a0, wq1.x); ffma2(acc[ 3], a0, wq1.y);
            ffma2(acc[ 4], a0, wq2.x); ffma2(acc[ 5], a0, wq2.y);
            ffma2(acc[ 6], a0, wq3.x); ffma2(acc[ 7], a0, wq3.y);
            ffma2(acc[ 8], a1, wq0.x); ffma2(acc[ 9], a1, wq0.y);
            ffma2(acc[10], a1, wq1.x); ffma2(acc[11], a1, wq1.y);
            ffma2(acc[12], a1, wq2.x); ffma2(acc[13], a1, wq2.y);
            ffma2(acc[14], a1, wq3.x); ffma2(acc[15], a1, wq3.y);
            ffma2(acc[16], a2, wq0.x); ffma2(acc[17], a2, wq0.y);
            ffma2(acc[18], a2, wq1.x); ffma2(acc[19], a2, wq1.y);
            ffma2(acc[20], a2, wq2.x); ffma2(acc[21], a2, wq2.y);
            ffma2(acc[22], a2, wq3.x); ffma2(acc[23], a2, wq3.y);
            ffma2(acc[24], a3, wq0.x); ffma2(acc[25], a3, wq0.y);
            ffma2(acc[26], a3, wq1.x); ffma2(acc[27], a3, wq1.y);
            ffma2(acc[28], a3, wq2.x); ffma2(acc[29], a3, wq2.y);
            ffma2(acc[30], a3, wq3.x); ffma2(acc[31], a3, wq3.y);
        }
    }

    // ---- epilogue: packed 8-byte stores, coalesced per half-warp ----
#pragma unroll
    for (int j = 0; j < 8; ++j) {
        int o = og*8 + j;
        float* orow = out + (((size_t)(b*OUTC) + o)*HH + y) * WW;
#pragma unroll
        for (int i2 = 0; i2 < 4; ++i2)
            *reinterpret_cast<unsigned long long*>(orow + pcol*2 + i2*32) =
                acc[i2*8+j];
    }
}

// ---------------------------------------------------------------------------
extern "C" void kernel_launch(void* const* d_in, const int* in_sizes, int n_in,
                              void* d_out, int out_size) {
    const float* x   = (const float*)d_in[0];
    const float* ow  = (const float*)d_in[1];
    const float* ob  = (const float*)d_in[2];
    const float* mw  = (const float*)d_in[3];
    const float* mb  = (const float*)d_in[4];
    const float* dw  = (const float*)d_in[5];
    const float* db  = (const float*)d_in[6];
    float* out = (float*)d_out;

    kW<<<64, 256>>>(ow, mw, dw);
    kA<<<BATCH*HH, 128>>>(x);
    kB<<<dim3(BATCH*HH, 2), 128>>>();
    kBc<<<NPOS/128, 128>>>(ob, mb);
    kC<<<BATCH*HH, 128>>>(db, out);
}

// round 10
// speedup vs baseline: 1.8066x; 1.8066x over previous
#include <cuda_runtime.h>
#include <cuda_bf16.h>

// Problem constants
#define BATCH 4
#define CIN   64
#define HH    128
#define WW    128
#define OUTC  64
#define K2N   9
#define NPOS  (BATCH*HH*WW)

// Scratch (device globals; no allocation allowed)
__device__ __align__(16) float g_xT[BATCH*HH*WW*CIN];   // [b][y][x][c]
__device__ __align__(16) float g_post[NPOS*28];         // partial half0, then final after combine
__device__ __align__(16) float g_post2[NPOS*28];        // partial half1
__device__ __align__(16) float g_cwT[9*64*28];          // [tap][c][j]
__device__ __align__(16) float g_dwT[9*64*64];          // [k][c][o]  (non-duplicated)

// ------------------------- f32x2 helpers (sm_100+) -------------------------
__device__ __forceinline__ void ffma2(unsigned long long& d,
                                      unsigned long long a,
                                      unsigned long long b) {
    asm("fma.rn.f32x2 %0, %1, %2, %0;" : "+l"(d) : "l"(a), "l"(b));
}
__device__ __forceinline__ unsigned long long dup2(float a) {
    unsigned long long r;
    asm("mov.b64 %0, {%1, %1};" : "=l"(r) : "f"(a));
    return r;
}

// ---------------------------------------------------------------------------
// Kernel W: weight transposes (tiny)
// ---------------------------------------------------------------------------
__global__ void kW(const float* __restrict__ ow, const float* __restrict__ mw,
                   const float* __restrict__ dw) {
    int i = blockIdx.x * blockDim.x + threadIdx.x;
    int stride = gridDim.x * blockDim.x;
    for (int idx = i; idx < 9*64*28; idx += stride) {
        int j   = idx % 28;
        int c   = (idx / 28) % 64;
        int tap = idx / (28*64);
        float v = 0.f;
        if (j < 18)      v = ow[j*576 + c*9 + tap];
        else if (j < 27) v = mw[(j-18)*576 + c*9 + tap];
        g_cwT[idx] = v;
    }
    // g_dwT[k][c][o] = dw[o][c][k]
    for (int idx = i; idx < 9*64*64; idx += stride) {
        int o = idx & 63;
        int c = (idx >> 6) & 63;
        int k = idx >> 12;
        g_dwT[idx] = dw[o*576 + c*9 + k];
    }
}

// ---------------------------------------------------------------------------
// Kernel A: NCHW -> NHWC transpose of x  (grid = BATCH*HH, block = 128)
// ---------------------------------------------------------------------------
__global__ __launch_bounds__(128) void kA(const float* __restrict__ x) {
    int by = blockIdx.x;
    int b = by >> 7, y = by & 127;
    int xq = threadIdx.x;
    const float* src = x + ((size_t)(b*CIN)*HH + y) * WW + xq;
    float* dst = g_xT + (((size_t)b*HH + y) * WW + xq) * CIN;
#pragma unroll
    for (int c4 = 0; c4 < 16; ++c4) {
        float4 v;
        v.x = src[(size_t)(c4*4+0)*HH*WW];
        v.y = src[(size_t)(c4*4+1)*HH*WW];
        v.z = src[(size_t)(c4*4+2)*HH*WW];
        v.w = src[(size_t)(c4*4+3)*HH*WW];
        *reinterpret_cast<float4*>(dst + c4*4) = v;
    }
}

// ---------------------------------------------------------------------------
// Kernel B: offset + mask conv partials over a 32-channel half.
// grid = dim3(512, 2). Writes RAW accumulators to g_post / g_post2.
// ---------------------------------------------------------------------------
__global__ __launch_bounds__(128) void kB() {
    __shared__ __align__(16) float sw[32*28];   // weights for one tap, 32 channels
    int by = blockIdx.x;
    int b = by >> 7, y = by & 127;
    int xq = threadIdx.x;
    int c0 = blockIdx.y * 32;
    float* gdst = blockIdx.y ? g_post2 : g_post;

    unsigned long long acc[14];
#pragma unroll
    for (int j = 0; j < 14; ++j) acc[j] = 0ULL;

    for (int tap = 0; tap < 9; ++tap) {
        __syncthreads();
        for (int t = threadIdx.x; t < 32*28/4; t += 128)
            reinterpret_cast<float4*>(sw)[t] =
                reinterpret_cast<const float4*>(g_cwT + tap*64*28 + c0*28)[t];
        __syncthreads();

        int ky = tap / 3, kx = tap % 3;
        int ys = y + ky - 1, xs = xq + kx - 1;
        if (ys < 0 || ys > 127 || xs < 0 || xs > 127) continue;  // zero pad

        const float4* xp = reinterpret_cast<const float4*>(
            g_xT + (((size_t)b*HH + ys) * WW + xs) * CIN + c0);
#pragma unroll 4
        for (int c4 = 0; c4 < 8; ++c4) {
            float4 xv = xp[c4];
#pragma unroll
            for (int cc = 0; cc < 4; ++cc) {
                unsigned long long ad = dup2((&xv.x)[cc]);
                const float4* wp = reinterpret_cast<const float4*>(sw + (c4*4+cc)*28);
#pragma unroll
                for (int j4 = 0; j4 < 7; ++j4) {
                    float4 w = wp[j4];
                    const unsigned long long* wu =
                        reinterpret_cast<const unsigned long long*>(&w);
                    ffma2(acc[j4*2+0], ad, wu[0]);
                    ffma2(acc[j4*2+1], ad, wu[1]);
                }
            }
        }
    }

    float* dst = gdst + (((size_t)(b*HH) + y) * WW + xq) * 28;
#pragma unroll
    for (int j2 = 0; j2 < 14; ++j2)
        *reinterpret_cast<unsigned long long*>(dst + 2*j2) = acc[j2];
}

// ---------------------------------------------------------------------------
// Kernel Bc: combine halves, add bias, sigmoid masks. In-place into g_post.
// ---------------------------------------------------------------------------
__global__ __launch_bounds__(128) void kBc(const float* __restrict__ ob,
                                           const float* __restrict__ mb) {
    size_t pos = (size_t)blockIdx.x * 128 + threadIdx.x;
    float* a = g_post + pos * 28;
    const float* bpart = g_post2 + pos * 28;
    float r[28];
#pragma unroll
    for (int q = 0; q < 7; ++q) {
        float4 va = reinterpret_cast<const float4*>(a)[q];
        float4 vb = reinterpret_cast<const float4*>(bpart)[q];
        r[4*q+0] = va.x + vb.x; r[4*q+1] = va.y + vb.y;
        r[4*q+2] = va.z + vb.z; r[4*q+3] = va.w + vb.w;
    }
#pragma unroll
    for (int j = 0; j < 18; ++j) r[j] += ob[j];
#pragma unroll
    for (int j = 0; j < 9; ++j) {
        float t = r[18+j] + mb[j];
        r[18+j] = 1.f / (1.f + __expf(-t));
    }
    r[27] = 0.f;
#pragma unroll
    for (int q = 0; q < 7; ++q)
        reinterpret_cast<float4*>(a)[q] =
            make_float4(r[4*q+0], r[4*q+1], r[4*q+2], r[4*q+3]);
}

// ---------------------------------------------------------------------------
// Kernel C: bilinear sampling + deform GEMM, FFMA2, single pass per k.
// grid = BATCH*HH, block = 128.
// Smem: A [64c][128pos] (32KB) + W non-dup [64c][64o] (16KB) = 48KB.
// Thread tile: 8 positions (4 strided x-pairs) x 8 outputs.
// Per c: 2 LDS.128 (W) + 4 LDS.64 (A pairs) + 8 dup2 MOV + 32 FFMA2.
// ---------------------------------------------------------------------------
__global__ __launch_bounds__(128) void kC(const float* __restrict__ db,
                                          float* __restrict__ out) {
    __shared__ __align__(16) float A_sh[64][128];
    __shared__ __align__(16) float W_sh[64][64];   // [c][o]

    int by = blockIdx.x;
    int b = by >> 7, y = by & 127;
    int tid  = threadIdx.x;
    int pcol = tid & 15;     // x pairs at pcol*2 + i2*32
    int og   = tid >> 4;     // outputs o = og*8 + j

    // acc[i2*8 + j] : f32x2 pair over two adjacent x, output o = og*8+j
    unsigned long long acc[32];
#pragma unroll
    for (int j = 0; j < 8; ++j) {
        unsigned long long bd = dup2(db[og*8 + j]);
#pragma unroll
        for (int i2 = 0; i2 < 4; ++i2) acc[i2*8+j] = bd;
    }

    const float* pi = g_post + (((size_t)(b*HH) + y) * WW + tid) * 28;

    for (int k = 0; k < 9; ++k) {
        __syncthreads();  // previous GEMM done reading A_sh / W_sh

        // ---- fill W slab for this k: 64*64 floats = 1024 float4, 8/thread ----
        {
            const float4* src = reinterpret_cast<const float4*>(g_dwT + (size_t)k*4096);
            float4* dst = reinterpret_cast<float4*>(&W_sh[0][0]);
#pragma unroll
            for (int t = 0; t < 8; ++t)
                dst[tid + t*128] = src[tid + t*128];
        }

        // ---- sampling: thread = position tid, write A_sh[c][tid] ----
        {
            float dy = pi[2*k], dx = pi[2*k+1], m = pi[18+k];
            int ky = k / 3, kx = k % 3;
            float py = dy + (float)(ky + y   - 1);
            float px = dx + (float)(kx + tid - 1);
            float fy = floorf(py), fx = floorf(px);
            float wy1 = py - fy, wx1 = px - fx;
            float wy0 = 1.f - wy1, wx0 = 1.f - wx1;
            int y0 = (int)fy, x0 = (int)fx;
            int y1 = y0 + 1, x1 = x0 + 1;
            bool vy0 = (y0 >= 0) & (y0 < HH), vy1 = (y1 >= 0) & (y1 < HH);
            bool vx0 = (x0 >= 0) & (x0 < WW), vx1 = (x1 >= 0) & (x1 < WW);
            float w00 = (vy0 && vx0) ? wy0*wx0*m : 0.f;
            float w01 = (vy0 && vx1) ? wy0*wx1*m : 0.f;
            float w10 = (vy1 && vx0) ? wy1*wx0*m : 0.f;
            float w11 = (vy1 && vx1) ? wy1*wx1*m : 0.f;
            int yc0 = min(max(y0, 0), HH-1), yc1 = min(max(y1, 0), HH-1);
            int xc0 = min(max(x0, 0), WW-1), xc1 = min(max(x1, 0), WW-1);

            const float4* p00 = reinterpret_cast<const float4*>(g_xT + (((size_t)b*HH + yc0)*WW + xc0)*CIN);
            const float4* p01 = reinterpret_cast<const float4*>(g_xT + (((size_t)b*HH + yc0)*WW + xc1)*CIN);
            const float4* p10 = reinterpret_cast<const float4*>(g_xT + (((size_t)b*HH + yc1)*WW + xc0)*CIN);
            const float4* p11 = reinterpret_cast<const float4*>(g_xT + (((size_t)b*HH + yc1)*WW + xc1)*CIN);

#pragma unroll 4
            for (int c4 = 0; c4 < 16; ++c4) {
                float4 a = p00[c4], bb = p01[c4], cv = p10[c4], d = p11[c4];
                A_sh[c4*4+0][tid] = w00*a.x + w01*bb.x + w10*cv.x + w11*d.x;
                A_sh[c4*4+1][tid] = w00*a.y + w01*bb.y + w10*cv.y + w11*d.y;
                A_sh[c4*4+2][tid] = w00*a.z + w01*bb.z + w10*cv.z + w11*d.z;
                A_sh[c4*4+3][tid] = w00*a.w + w01*bb.w + w10*cv.w + w11*d.w;
            }
        }

        __syncthreads();  // A + W ready

        // ---- GEMM: 64 c; per c: 6 LDS + 8 MOV + 32 FFMA2 ----
#pragma unroll 2
        for (int c = 0; c < 64; ++c) {
            const float4* wf = reinterpret_cast<const float4*>(&W_sh[c][og*8]);
            float4 wlo = wf[0], whi = wf[1];
            unsigned long long w0 = dup2(wlo.x), w1 = dup2(wlo.y);
            unsigned long long w2 = dup2(wlo.z), w3 = dup2(wlo.w);
            unsigned long long w4 = dup2(whi.x), w5 = dup2(whi.y);
            unsigned long long w6 = dup2(whi.z), w7 = dup2(whi.w);

            const float* ac = &A_sh[c][pcol*2];
            unsigned long long a0 = *reinterpret_cast<const unsigned long long*>(ac);
            unsigned long long a1 = *reinterpret_cast<const unsigned long long*>(ac + 32);
            unsigned long long a2 = *reinterpret_cast<const unsigned long long*>(ac + 64);
            unsigned long long a3 = *reinterpret_cast<const unsigned long long*>(ac + 96);

            ffma2(acc[ 0], a0, w0); ffma2(acc[ 1], a0, w1);
            ffma2(acc[ 2], a0, w2); ffma2(acc[ 3], a0, w3);
            ffma2(acc[ 4], a0, w4); ffma2(acc[ 5], a0, w5);
            ffma2(acc[ 6], a0, w6); ffma2(acc[ 7], a0, w7);
            ffma2(acc[ 8], a1, w0); ffma2(acc[ 9], a1, w1);
            ffma2(acc[10], a1, w2); ffma2(acc[11], a1, w3);
            ffma2(acc[12], a1, w4); ffma2(acc[13], a1, w5);
            ffma2(acc[14], a1, w6); ffma2(acc[15], a1, w7);
            ffma2(acc[16], a2, w0); ffma2(acc[17], a2, w1);
            ffma2(acc[18], a2, w2); ffma2(acc[19], a2, w3);
            ffma2(acc[20], a2, w4); ffma2(acc[21], a2, w5);
            ffma2(acc[22], a2, w6); ffma2(acc[23], a2, w7);
            ffma2(acc[24], a3, w0); ffma2(acc[25], a3, w1);
            ffma2(acc[26], a3, w2); ffma2(acc[27], a3, w3);
            ffma2(acc[28], a3, w4); ffma2(acc[29], a3, w5);
            ffma2(acc[30], a3, w6); ffma2(acc[31], a3, w7);
        }
    }

    // ---- epilogue: packed 8-byte stores, coalesced per half-warp ----
#pragma unroll
    for (int j = 0; j < 8; ++j) {
        int o = og*8 + j;
        float* orow = out + (((size_t)(b*OUTC) + o)*HH + y) * WW;
#pragma unroll
        for (int i2 = 0; i2 < 4; ++i2)
            *reinterpret_cast<unsigned long long*>(orow + pcol*2 + i2*32) =
                acc[i2*8+j];
    }
}

// ---------------------------------------------------------------------------
extern "C" void kernel_launch(void* const* d_in, const int* in_sizes, int n_in,
                              void* d_out, int out_size) {
    const float* x   = (const float*)d_in[0];
    const float* ow  = (const float*)d_in[1];
    const float* ob  = (const float*)d_in[2];
    const float* mw  = (const float*)d_in[3];
    const float* mb  = (const float*)d_in[4];
    const float* dw  = (const float*)d_in[5];
    const float* db  = (const float*)d_in[6];
    float* out = (float*)d_out;

    kW<<<64, 256>>>(ow, mw, dw);
    kA<<<BATCH*HH, 128>>>(x);
    kB<<<dim3(BATCH*HH, 2), 128>>>();
    kBc<<<NPOS/128, 128>>>(ob, mb);
    kC<<<BATCH*HH, 128>>>(db, out);
}